// round 5
// baseline (speedup 1.0000x reference)
#include <cuda_runtime.h>
#include <cstdint>

#define N_PULSES 64
#define N_STATES 21

typedef unsigned long long u64;

// ---- packed f32x2 helpers (Blackwell sm_103a; FFMA2/FMUL2/FADD2 via PTX only) ----
__device__ __forceinline__ u64 pk(float lo, float hi) {
    u64 r; asm("mov.b64 %0, {%1, %2};" : "=l"(r) : "f"(lo), "f"(hi)); return r;
}
__device__ __forceinline__ void unpk(u64 v, float& lo, float& hi) {
    asm("mov.b64 {%0, %1}, %2;" : "=f"(lo), "=f"(hi) : "l"(v));
}
__device__ __forceinline__ u64 fma2(u64 a, u64 b, u64 c) {
    u64 r; asm("fma.rn.f32x2 %0, %1, %2, %3;" : "=l"(r) : "l"(a), "l"(b), "l"(c)); return r;
}
__device__ __forceinline__ u64 mul2(u64 a, u64 b) {
    u64 r; asm("mul.rn.f32x2 %0, %1, %2;" : "=l"(r) : "l"(a), "l"(b)); return r;
}

__global__ __launch_bounds__(256)
void epg_kernel(const float* __restrict__ flip,
                const float* __restrict__ phases,
                const float* __restrict__ T1,
                const float* __restrict__ T2,
                const float* __restrict__ B0,
                const float* __restrict__ B1,
                const void*  __restrict__ trp,
                float* __restrict__ out,
                int B)
{
    // Per-pulse constants: positives (cb, sb, c2b, s2b), negatives, half flip angle
    __shared__ float4 s_c[N_PULSES];
    __shared__ float4 s_n[N_PULSES];
    __shared__ float  s_ha[N_PULSES];

    int tid = threadIdx.x;
    if (tid < N_PULSES) {
        float bph = phases[tid];
        float sb, cb;
        sincosf(bph, &sb, &cb);
        float c2b = cb * cb - sb * sb;
        float s2b = 2.0f * cb * sb;
        s_c[tid]  = make_float4(cb, sb, c2b, s2b);
        s_n[tid]  = make_float4(-cb, -sb, -c2b, -s2b);
        s_ha[tid] = 0.5f * flip[tid];
    }
    __syncthreads();

    int gwarp = (int)((blockIdx.x * blockDim.x + tid) >> 5);
    int lane  = tid & 31;

    // Each warp simulates TWO independent batch elements packed into f32x2 lanes
    int b0 = 2 * gwarp;
    int b1 = b0 + 1;
    if (b0 >= B) return;
    bool has1 = (b1 < B);
    int b1c = has1 ? b1 : b0;

    // TR: defensive decode (int32 / float32 both yield 500)
    float TRf;
    {
        int iv = *(const int*)trp;
        if (iv > 0 && iv < 1000000) TRf = (float)iv;
        else                        TRf = *(const float*)trp;
    }

    float E1a = expf(-TRf / T1[b0]);
    float E1b = expf(-TRf / T1[b1c]);
    float E2a = expf(-TRf / T2[b0]);
    float E2b = expf(-TRf / T2[b1c]);
    float b1va = B1[b0];
    float b1vb = B1[b1c];

    const float TWO_PI_OVER_1000 = 6.283185307179586e-3f;
    float sphA, cphA, sphB, cphB;
    sincosf(TWO_PI_OVER_1000 * B0[b0]  * TRf, &sphA, &cphA);
    sincosf(TWO_PI_OVER_1000 * B0[b1c] * TRf, &sphB, &cphB);

    // Packed per-thread constants
    u64 E1p   = pk(E1a, E1b);
    u64 cE    = pk(E2a * cphA,  E2b * cphB);
    u64 sE    = pk(E2a * sphA,  E2b * sphB);
    u64 nsE   = pk(-E2a * sphA, -E2b * sphB);
    u64 recov = (lane == 0) ? pk(1.0f - E1a, 1.0f - E1b) : 0ull;
    u64 NEG1  = pk(-1.0f, -1.0f);

    // Packed state
    u64 FpR = 0ull, FpI = 0ull, FmR = 0ull, FmI = 0ull;
    u64 Z = (lane == 0) ? pk(1.0f, 1.0f) : 0ull;

    size_t planeStride = (size_t)B * N_STATES;
    size_t pulseStride = 5 * planeStride;
    float* outp = out + (size_t)b0 * N_STATES + lane;   // element b1 = outp + N_STATES
    bool st0 = (lane < N_STATES);
    bool st1 = st0 && has1;
    bool isLane0 = (lane == 0);
    bool isLast  = (lane == N_STATES - 1);

    #pragma unroll 2
    for (int p = 0; p < N_PULSES; p++) {
        // ---- fused E2 relaxation + B0 rotation (packed complex multiplies) ----
        u64 t;
        t   = fma2(FpR, cE, mul2(FpI, nsE));
        FpI = fma2(FpI, cE, mul2(FpR, sE));
        FpR = t;
        t   = fma2(FmR, cE, mul2(FmI, sE));
        FmI = fma2(FmI, cE, mul2(FmR, nsE));
        FmR = t;

        // Z relaxation + recovery (recov is 0 except lane 0)
        Z = fma2(Z, E1p, recov);

        // ---- RF mixing ----
        float ha = s_ha[p];
        float4 c = s_c[p];
        float4 n = s_n[p];
        u64 cbp  = pk(c.x, c.x), sbp  = pk(c.y, c.y);
        u64 c2bp = pk(c.z, c.z), s2bp = pk(c.w, c.w);
        u64 ncbp = pk(n.x, n.x), nsbp = pk(n.y, n.y);
        u64 nc2bp= pk(n.z, n.z), ns2bp= pk(n.w, n.w);

        float saA, caA, saB, caB;
        __sincosf(ha * b1va, &saA, &caA);
        __sincosf(ha * b1vb, &saB, &caB);
        u64 ca = pk(caA, caB);
        u64 sa = pk(saA, saB);

        u64 ca2  = mul2(ca, ca);
        u64 sa2  = mul2(sa, sa);
        u64 casa = mul2(ca, sa);
        u64 cZ   = mul2(casa, Z);
        u64 nsa  = mul2(sa, NEG1);
        u64 d    = fma2(sa, nsa, ca2);       // cos^2 - sin^2

        u64 FpnR = fma2(ca2, FpR, fma2(sa2, fma2(FmR, c2bp,  mul2(FmI, s2bp)),  mul2(cZ, nsbp)));
        u64 FpnI = fma2(ca2, FpI, fma2(sa2, fma2(FmR, s2bp,  mul2(FmI, nc2bp)), mul2(cZ, cbp)));
        u64 FmnR = fma2(ca2, FmR, fma2(sa2, fma2(FpR, c2bp,  mul2(FpI, ns2bp)), mul2(cZ, nsbp)));
        u64 FmnI = fma2(ca2, FmI, fma2(sa2, fma2(FpR, ns2bp, mul2(FpI, nc2bp)), mul2(cZ, ncbp)));
        u64 Dim  = fma2(FpI, cbp, fma2(FpR, nsbp, fma2(FmR, nsbp, mul2(FmI, ncbp))));
        u64 Zn   = fma2(casa, Dim, mul2(d, Z));

        // ---- gradient shift via shuffles on unpacked halves ----
        float pr0, pr1, pi0, pi1, mr0, mr1, mi0, mi1;
        unpk(FpnR, pr0, pr1);
        unpk(FpnI, pi0, pi1);
        unpk(FmnR, mr0, mr1);
        unpk(FmnI, mi0, mi1);

        float uR0 = __shfl_up_sync  (0xffffffffu, pr0, 1);
        float uR1 = __shfl_up_sync  (0xffffffffu, pr1, 1);
        float uI0 = __shfl_up_sync  (0xffffffffu, pi0, 1);
        float uI1 = __shfl_up_sync  (0xffffffffu, pi1, 1);
        float dR0 = __shfl_down_sync(0xffffffffu, mr0, 1);
        float dR1 = __shfl_down_sync(0xffffffffu, mr1, 1);
        float dI0 = __shfl_down_sync(0xffffffffu, mi0, 1);
        float dI1 = __shfl_down_sync(0xffffffffu, mi1, 1);
        if (isLane0) { uR0 = 0.f; uR1 = 0.f; uI0 = 0.f; uI1 = 0.f; }
        if (isLast)  { dR0 = 0.f; dR1 = 0.f; dI0 = 0.f; dI1 = 0.f; }

        FpR = pk(uR0, uR1);
        FpI = pk(uI0, uI1);
        FmR = pk(dR0, dR1);
        FmI = pk(dI0, dI1);
        Z = Zn;

        // ---- stores: outs[p, comp, b, state] ----
        float z0, z1;
        unpk(Zn, z0, z1);
        if (st0) {
            outp[0]               = uR0;
            outp[planeStride]     = uI0;
            outp[2 * planeStride] = dR0;
            outp[3 * planeStride] = dI0;
            outp[4 * planeStride] = z0;
        }
        if (st1) {
            float* o1 = outp + N_STATES;
            o1[0]               = uR1;
            o1[planeStride]     = uI1;
            o1[2 * planeStride] = dR1;
            o1[3 * planeStride] = dI1;
            o1[4 * planeStride] = z1;
        }
        outp += pulseStride;
    }
}

extern "C" void kernel_launch(void* const* d_in, const int* in_sizes, int n_in,
                              void* d_out, int out_size)
{
    const float* flip   = (const float*)d_in[0];
    const float* phases = (const float*)d_in[1];
    const float* T1     = (const float*)d_in[2];
    const float* T2     = (const float*)d_in[3];
    const float* B0     = (const float*)d_in[4];
    const float* B1     = (const float*)d_in[5];
    const void*  trp    = d_in[6];
    float* out = (float*)d_out;

    int B = in_sizes[2];               // batch from T1
    int threads = 256;
    int warpsPerBlock = threads / 32;  // 8
    int elemsPerBlock = warpsPerBlock * 2;
    int blocks = (B + elemsPerBlock - 1) / elemsPerBlock;

    epg_kernel<<<blocks, threads>>>(flip, phases, T1, T2, B0, B1, trp, out, B);
}